// round 3
// baseline (speedup 1.0000x reference)
#include <cuda_runtime.h>

// Problem constants (fixed-shape problem)
#define WIN   48
#define DIN   64
#define DOUT  128
#define BATCH 4096
#define NSEG  (BATCH * WIN)      // 196608 segments
#define NEV_MAX 2000000
#define SCAN_BLK 2048            // elems per scan block
#define SCAN_NBLK (NSEG / SCAN_BLK)   // 96

// Scratch
__device__ int g_cnt[NSEG];            // events per segment
__device__ int g_cur[NSEG];            // exclusive offsets (then cursors -> end)
__device__ int g_part[SCAN_NBLK];      // scan partials (block totals)
__device__ int g_bucket[NEV_MAX];      // event ids grouped by segment

// ---------------------------------------------------------------------------
// 1) zero counters
// ---------------------------------------------------------------------------
__global__ void zero_cnt_kernel() {
    int i = blockIdx.x * blockDim.x + threadIdx.x;
    if (i < NSEG) g_cnt[i] = 0;
}

// ---------------------------------------------------------------------------
// 2) histogram: events per segment
// ---------------------------------------------------------------------------
__global__ void hist_kernel(const int* __restrict__ bi,
                            const int* __restrict__ wi, int n) {
    int i = blockIdx.x * blockDim.x + threadIdx.x;
    if (i >= n) return;
    int seg = bi[i] * WIN + wi[i];
    atomicAdd(&g_cnt[seg], 1);
}

// ---------------------------------------------------------------------------
// 3a) per-2048-block exclusive scan; block totals -> g_part
// ---------------------------------------------------------------------------
__global__ __launch_bounds__(1024) void scan_a_kernel() {
    __shared__ int warp_tot[32];
    int tid = threadIdx.x;
    int base = blockIdx.x * SCAN_BLK;
    int a = g_cnt[base + 2 * tid];
    int b = g_cnt[base + 2 * tid + 1];
    int s = a + b;
    int lane = tid & 31, wid = tid >> 5;
    int v = s;
    #pragma unroll
    for (int o = 1; o < 32; o <<= 1) {
        int t = __shfl_up_sync(0xffffffffu, v, o);
        if (lane >= o) v += t;
    }
    if (lane == 31) warp_tot[wid] = v;
    __syncthreads();
    if (wid == 0) {
        int w = warp_tot[lane];
        #pragma unroll
        for (int o = 1; o < 32; o <<= 1) {
            int t = __shfl_up_sync(0xffffffffu, w, o);
            if (lane >= o) w += t;
        }
        warp_tot[lane] = w;   // inclusive warp totals
    }
    __syncthreads();
    int warp_off = (wid == 0) ? 0 : warp_tot[wid - 1];
    int incl = v + warp_off;              // inclusive over block (this pair)
    g_cur[base + 2 * tid]     = incl - s; // exclusive for a
    g_cur[base + 2 * tid + 1] = incl - b; // exclusive for b
    if (tid == 1023) g_part[blockIdx.x] = incl;
}

// ---------------------------------------------------------------------------
// 3b) add global prefix: each 256-block computes sum of g_part[0..sb) itself
//     with a warp-parallel reduction (replaces serial scan_b + scan_c)
// ---------------------------------------------------------------------------
__global__ __launch_bounds__(256) void scan_c_kernel() {
    __shared__ int s_off;
    int blk = blockIdx.x;
    int sb = blk >> 3;                // which 2048-scan-block we belong to
    if (threadIdx.x < 32) {
        int acc = 0;
        for (int i = threadIdx.x; i < sb; i += 32) acc += g_part[i];
        #pragma unroll
        for (int o = 16; o > 0; o >>= 1)
            acc += __shfl_down_sync(0xffffffffu, acc, o);
        if (threadIdx.x == 0) s_off = acc;
    }
    __syncthreads();
    g_cur[blk * 256 + threadIdx.x] += s_off;
}

// ---------------------------------------------------------------------------
// 4) scatter event indices into buckets (g_cur becomes END offset)
// ---------------------------------------------------------------------------
__global__ void scatter_idx_kernel(const int* __restrict__ bi,
                                   const int* __restrict__ wi, int n) {
    int i = blockIdx.x * blockDim.x + threadIdx.x;
    if (i >= n) return;
    int seg = bi[i] * WIN + wi[i];
    int pos = atomicAdd(&g_cur[seg], 1);
    g_bucket[pos] = i;
}

// ---------------------------------------------------------------------------
// 5) fused: gather-reduce -> mean -> GEMM(64x128) -> +bias -> permute
//    One block per batch. 8 warps; warp wg owns segments wg*6..wg*6+5:
//    it gathers their event rows, builds means in smem, then computes the
//    GEMM tile that consumes exactly those 6 windows.
// ---------------------------------------------------------------------------
__device__ __forceinline__ void unpack2(unsigned long long v, float& lo, float& hi) {
    asm("mov.b64 {%0, %1}, %2;" : "=f"(lo), "=f"(hi) : "l"(v));
}
__device__ __forceinline__ void fma2(unsigned long long& acc, float m,
                                     unsigned long long w) {
    unsigned long long mm;
    asm("mov.b64 %0, {%1, %1};" : "=l"(mm) : "f"(m));
    asm("fma.rn.f32x2 %0, %1, %2, %0;" : "+l"(acc) : "l"(mm), "l"(w));
}

__global__ __launch_bounds__(256) void fused_pool_kernel(
    const float* __restrict__ in,     // [N][DIN]
    const float* __restrict__ Wm,     // [DIN][DOUT] row-major (k-major)
    const float* __restrict__ bias,   // [DOUT]
    float*       __restrict__ out)    // [BATCH][DOUT][WIN]
{
    __shared__ float s_mean[WIN * DIN];   // 3072 floats
    __shared__ float s_w[DIN * DOUT];     // 8192 floats; reused as out[128][49]
    __shared__ float s_b[DOUT];
    __shared__ float s_has[WIN];

    int b   = blockIdx.x;
    int tid = threadIdx.x;
    int lane = tid & 31;
    int wg   = tid >> 5;

    if (tid < DOUT) s_b[tid] = bias[tid];

    // ---- load W (coalesced float4) ----
    {
        const float4* w4 = reinterpret_cast<const float4*>(Wm);
        float4* sw4 = reinterpret_cast<float4*>(s_w);
        #pragma unroll
        for (int i = tid; i < DIN * DOUT / 4; i += 256) sw4[i] = w4[i];
    }

    // ---- gather-reduce 6 segments per warp; write means to smem ----
    #pragma unroll 1
    for (int si = 0; si < 6; si++) {
        int s   = wg * 6 + si;
        int seg = b * WIN + s;
        int cnt   = g_cnt[seg];
        int end   = g_cur[seg];      // after scatter, cur == start + cnt
        int start = end - cnt;

        float a0 = 0.f, a1 = 0.f;
        int i = start;
        for (; i + 1 < end; i += 2) {
            int e0 = __ldcs(&g_bucket[i]);
            int e1 = __ldcs(&g_bucket[i + 1]);
            const float* r0 = in + (size_t)e0 * DIN;
            const float* r1 = in + (size_t)e1 * DIN;
            float x0 = __ldcs(r0 + lane);
            float x1 = __ldcs(r0 + lane + 32);
            float y0 = __ldcs(r1 + lane);
            float y1 = __ldcs(r1 + lane + 32);
            a0 += x0 + y0;
            a1 += x1 + y1;
        }
        if (i < end) {
            int e = __ldcs(&g_bucket[i]);
            const float* r = in + (size_t)e * DIN;
            a0 += __ldcs(r + lane);
            a1 += __ldcs(r + lane + 32);
        }
        float inv = (cnt > 0) ? (1.f / (float)cnt) : 0.f;
        s_mean[s * DIN + lane]      = a0 * inv;
        s_mean[s * DIN + lane + 32] = a1 * inv;
        if (lane == 0) s_has[s] = (cnt > 0) ? 1.f : 0.f;
    }
    __syncthreads();   // W + all means ready

    // ---- compute 6w x 4d tile per thread ----
    int dg = lane;
    int d0 = dg * 2;

    unsigned long long acc0[6], acc1[6];
    #pragma unroll
    for (int i = 0; i < 6; i++) { acc0[i] = 0ull; acc1[i] = 0ull; }

    const float* mbase = s_mean + wg * 6 * DIN;

    #pragma unroll
    for (int kk = 0; kk < 16; kk++) {
        int k = kk * 4;
        float4 m[6];
        #pragma unroll
        for (int i = 0; i < 6; i++)
            m[i] = *reinterpret_cast<const float4*>(mbase + i * DIN + k);
        #pragma unroll
        for (int j = 0; j < 4; j++) {
            unsigned long long w0 = *reinterpret_cast<const unsigned long long*>(
                s_w + (k + j) * DOUT + d0);
            unsigned long long w1 = *reinterpret_cast<const unsigned long long*>(
                s_w + (k + j) * DOUT + 64 + d0);
            #pragma unroll
            for (int i = 0; i < 6; i++) {
                float mv = (j == 0) ? m[i].x : (j == 1) ? m[i].y
                         : (j == 2) ? m[i].z : m[i].w;
                fma2(acc0[i], mv, w0);
                fma2(acc1[i], mv, w1);
            }
        }
    }

    __syncthreads();   // everyone done reading s_w; reuse as out staging

    // ---- stage results as out[d][w] pad-49 (+bias if nonempty) ----
    float b0x = s_b[d0],      b0y = s_b[d0 + 1];
    float b1x = s_b[d0 + 64], b1y = s_b[d0 + 65];
    #pragma unroll
    for (int i = 0; i < 6; i++) {
        int w = wg * 6 + i;
        float has = s_has[w];
        float a0x, a0y, a1x, a1y;
        unpack2(acc0[i], a0x, a0y);
        unpack2(acc1[i], a1x, a1y);
        s_w[(d0    ) * 49 + w] = a0x + has * b0x;
        s_w[(d0 + 1) * 49 + w] = a0y + has * b0y;
        s_w[(d0 + 64) * 49 + w] = a1x + has * b1x;
        s_w[(d0 + 65) * 49 + w] = a1y + has * b1y;
    }
    __syncthreads();

    // ---- coalesced float4 store of out[b][d][w] ----
    float* obase = out + (size_t)b * DOUT * WIN;
    #pragma unroll
    for (int it = 0; it < 6; it++) {
        int j = it * 1024 + tid * 4;   // 48 % 4 == 0 -> all 4 elems share d
        int d = j / 48;
        int w = j - d * 48;
        const float* src = s_w + d * 49 + w;
        float4 v = make_float4(src[0], src[1], src[2], src[3]);
        *reinterpret_cast<float4*>(obase + j) = v;
    }
}

// ---------------------------------------------------------------------------
extern "C" void kernel_launch(void* const* d_in, const int* in_sizes, int n_in,
                              void* d_out, int out_size) {
    const float* input = (const float*)d_in[0];
    const float* Wm    = (const float*)d_in[1];
    const float* bias  = (const float*)d_in[2];

    const int* bi;
    const int* wi;
    int n_events;
    if (n_in >= 6 && in_sizes[3] == 1) {
        bi = (const int*)d_in[4];
        wi = (const int*)d_in[5];
        n_events = in_sizes[4];
    } else {
        bi = (const int*)d_in[3];
        wi = (const int*)d_in[4];
        n_events = in_sizes[3];
    }

    int eb = (n_events + 255) / 256;

    zero_cnt_kernel<<<(NSEG + 255) / 256, 256>>>();
    hist_kernel<<<eb, 256>>>(bi, wi, n_events);
    scan_a_kernel<<<SCAN_NBLK, 1024>>>();
    scan_c_kernel<<<NSEG / 256, 256>>>();
    scatter_idx_kernel<<<eb, 256>>>(bi, wi, n_events);
    fused_pool_kernel<<<BATCH, 256>>>(input, Wm, bias, (float*)d_out);
}

// round 5
// speedup vs baseline: 1.5586x; 1.5586x over previous
#include <cuda_runtime.h>

// Problem constants (fixed-shape problem)
#define WIN   48
#define DIN   64
#define DOUT  128
#define BATCH 4096
#define NSEG  (BATCH * WIN)      // 196608 segments
#define NEV_MAX 2000000
#define SCAN_BLK 2048            // elems per scan block
#define SCAN_NBLK (NSEG / SCAN_BLK)   // 96

// Scratch
__device__ int   g_cnt[NSEG];            // events per segment
__device__ int   g_cur[NSEG];            // exclusive offsets (then cursors -> end)
__device__ int   g_part[SCAN_NBLK];      // scan partials (block totals)
__device__ int   g_bucket[NEV_MAX];      // event ids grouped by segment
__device__ float g_mean[NSEG * DIN];     // segment means (written, never atomically)

// ---------------------------------------------------------------------------
// 1) zero counters
// ---------------------------------------------------------------------------
__global__ void zero_cnt_kernel() {
    int i = blockIdx.x * blockDim.x + threadIdx.x;
    if (i < NSEG) g_cnt[i] = 0;
}

// ---------------------------------------------------------------------------
// 2) histogram: events per segment
// ---------------------------------------------------------------------------
__global__ void hist_kernel(const int* __restrict__ bi,
                            const int* __restrict__ wi, int n) {
    int i = blockIdx.x * blockDim.x + threadIdx.x;
    if (i >= n) return;
    int seg = bi[i] * WIN + wi[i];
    atomicAdd(&g_cnt[seg], 1);
}

// ---------------------------------------------------------------------------
// 3a) per-2048-block exclusive scan; block totals -> g_part
// ---------------------------------------------------------------------------
__global__ __launch_bounds__(1024) void scan_a_kernel() {
    __shared__ int warp_tot[32];
    int tid = threadIdx.x;
    int base = blockIdx.x * SCAN_BLK;
    int a = g_cnt[base + 2 * tid];
    int b = g_cnt[base + 2 * tid + 1];
    int s = a + b;
    int lane = tid & 31, wid = tid >> 5;
    int v = s;
    #pragma unroll
    for (int o = 1; o < 32; o <<= 1) {
        int t = __shfl_up_sync(0xffffffffu, v, o);
        if (lane >= o) v += t;
    }
    if (lane == 31) warp_tot[wid] = v;
    __syncthreads();
    if (wid == 0) {
        int w = warp_tot[lane];
        #pragma unroll
        for (int o = 1; o < 32; o <<= 1) {
            int t = __shfl_up_sync(0xffffffffu, w, o);
            if (lane >= o) w += t;
        }
        warp_tot[lane] = w;   // inclusive warp totals
    }
    __syncthreads();
    int warp_off = (wid == 0) ? 0 : warp_tot[wid - 1];
    int incl = v + warp_off;              // inclusive over block (this pair)
    g_cur[base + 2 * tid]     = incl - s; // exclusive for a
    g_cur[base + 2 * tid + 1] = incl - b; // exclusive for b
    if (tid == 1023) g_part[blockIdx.x] = incl;
}

// ---------------------------------------------------------------------------
// 3b) add global prefix: each 256-block computes sum of g_part[0..sb) itself
//     with a warp-parallel reduction (no serial pass)
// ---------------------------------------------------------------------------
__global__ __launch_bounds__(256) void scan_c_kernel() {
    __shared__ int s_off;
    int blk = blockIdx.x;
    int sb = blk >> 3;                // which 2048-scan-block we belong to
    if (threadIdx.x < 32) {
        int acc = 0;
        for (int i = threadIdx.x; i < sb; i += 32) acc += g_part[i];
        #pragma unroll
        for (int o = 16; o > 0; o >>= 1)
            acc += __shfl_down_sync(0xffffffffu, acc, o);
        if (threadIdx.x == 0) s_off = acc;
    }
    __syncthreads();
    g_cur[blk * 256 + threadIdx.x] += s_off;
}

// ---------------------------------------------------------------------------
// 4) scatter event indices into buckets (g_cur becomes END offset)
// ---------------------------------------------------------------------------
__global__ void scatter_idx_kernel(const int* __restrict__ bi,
                                   const int* __restrict__ wi, int n) {
    int i = blockIdx.x * blockDim.x + threadIdx.x;
    if (i >= n) return;
    int seg = bi[i] * WIN + wi[i];
    int pos = atomicAdd(&g_cur[seg], 1);
    g_bucket[pos] = i;
}

// ---------------------------------------------------------------------------
// 5) gather-reduce: one warp per segment, no atomics, unroll-4 (MLP ~8).
//    Writes MEANS directly; empty segments write zeros.
// ---------------------------------------------------------------------------
__global__ __launch_bounds__(256) void reduce_kernel(const float* __restrict__ in) {
    int seg  = (blockIdx.x * blockDim.x + threadIdx.x) >> 5;
    int lane = threadIdx.x & 31;
    if (seg >= NSEG) return;

    int cnt   = g_cnt[seg];
    int end   = g_cur[seg];       // after scatter, cur == start + cnt
    int start = end - cnt;

    float a0 = 0.f, a1 = 0.f;
    int i = start;
    for (; i + 3 < end; i += 4) {          // 8 outstanding 128B row loads
        int e0 = __ldcs(&g_bucket[i]);
        int e1 = __ldcs(&g_bucket[i + 1]);
        int e2 = __ldcs(&g_bucket[i + 2]);
        int e3 = __ldcs(&g_bucket[i + 3]);
        const float* r0 = in + (size_t)e0 * DIN;
        const float* r1 = in + (size_t)e1 * DIN;
        const float* r2 = in + (size_t)e2 * DIN;
        const float* r3 = in + (size_t)e3 * DIN;
        float x0 = __ldcs(r0 + lane);
        float x1 = __ldcs(r0 + lane + 32);
        float y0 = __ldcs(r1 + lane);
        float y1 = __ldcs(r1 + lane + 32);
        float z0 = __ldcs(r2 + lane);
        float z1 = __ldcs(r2 + lane + 32);
        float w0 = __ldcs(r3 + lane);
        float w1 = __ldcs(r3 + lane + 32);
        a0 += (x0 + y0) + (z0 + w0);
        a1 += (x1 + y1) + (z1 + w1);
    }
    for (; i < end; i++) {
        int e = __ldcs(&g_bucket[i]);
        const float* r = in + (size_t)e * DIN;
        a0 += __ldcs(r + lane);
        a1 += __ldcs(r + lane + 32);
    }
    float inv = (cnt > 0) ? (1.f / (float)cnt) : 0.f;
    g_mean[(size_t)seg * DIN + lane]      = a0 * inv;
    g_mean[(size_t)seg * DIN + lane + 32] = a1 * inv;
}

// ---------------------------------------------------------------------------
// 6) per-batch fused  GEMM(means @ W) -> +bias(if nonempty) -> permute
// ---------------------------------------------------------------------------
__device__ __forceinline__ void unpack2(unsigned long long v, float& lo, float& hi) {
    asm("mov.b64 {%0, %1}, %2;" : "=f"(lo), "=f"(hi) : "l"(v));
}
__device__ __forceinline__ void fma2(unsigned long long& acc, float m,
                                     unsigned long long w) {
    unsigned long long mm;
    asm("mov.b64 %0, {%1, %1};" : "=l"(mm) : "f"(m));
    asm("fma.rn.f32x2 %0, %1, %2, %0;" : "+l"(acc) : "l"(mm), "l"(w));
}

__global__ __launch_bounds__(256) void pool_gemm_kernel(
    const float* __restrict__ Wm,     // [DIN][DOUT] row-major (k-major)
    const float* __restrict__ bias,   // [DOUT]
    float*       __restrict__ out)    // [BATCH][DOUT][WIN]
{
    __shared__ float s_mean[WIN * DIN];   // 3072 floats
    __shared__ float s_w[DIN * DOUT];     // 8192 floats; reused as out[128][49]
    __shared__ float s_b[DOUT];
    __shared__ float s_has[WIN];

    int b   = blockIdx.x;
    int tid = threadIdx.x;

    if (tid < WIN) s_has[tid] = (g_cnt[b * WIN + tid] > 0) ? 1.f : 0.f;
    if (tid < DOUT) s_b[tid] = bias[tid];

    // ---- load W (coalesced float4) ----
    {
        const float4* w4 = reinterpret_cast<const float4*>(Wm);
        float4* sw4 = reinterpret_cast<float4*>(s_w);
        #pragma unroll
        for (int i = tid; i < DIN * DOUT / 4; i += 256) sw4[i] = w4[i];
    }

    // ---- load means (already divided) ----
    {
        const float4* srow = reinterpret_cast<const float4*>(
            g_mean + (size_t)b * WIN * DIN);
        float4* sm4 = reinterpret_cast<float4*>(s_mean);
        #pragma unroll
        for (int i = tid; i < WIN * DIN / 4; i += 256) sm4[i] = srow[i];
    }
    __syncthreads();   // means + W ready

    // ---- compute 6w x 4d tile per thread ----
    int dg = tid & 31;
    int wg = tid >> 5;
    int d0 = dg * 2;

    unsigned long long acc0[6], acc1[6];
    #pragma unroll
    for (int i = 0; i < 6; i++) { acc0[i] = 0ull; acc1[i] = 0ull; }

    const float* mbase = s_mean + wg * 6 * DIN;

    #pragma unroll
    for (int kk = 0; kk < 16; kk++) {
        int k = kk * 4;
        float4 m[6];
        #pragma unroll
        for (int i = 0; i < 6; i++)
            m[i] = *reinterpret_cast<const float4*>(mbase + i * DIN + k);
        #pragma unroll
        for (int j = 0; j < 4; j++) {
            unsigned long long w0 = *reinterpret_cast<const unsigned long long*>(
                s_w + (k + j) * DOUT + d0);
            unsigned long long w1 = *reinterpret_cast<const unsigned long long*>(
                s_w + (k + j) * DOUT + 64 + d0);
            #pragma unroll
            for (int i = 0; i < 6; i++) {
                float mv = (j == 0) ? m[i].x : (j == 1) ? m[i].y
                         : (j == 2) ? m[i].z : m[i].w;
                fma2(acc0[i], mv, w0);
                fma2(acc1[i], mv, w1);
            }
        }
    }

    __syncthreads();   // everyone done reading s_w; reuse as out staging

    // ---- stage results as out[d][w] pad-49 (+bias if nonempty) ----
    float b0x = s_b[d0],      b0y = s_b[d0 + 1];
    float b1x = s_b[d0 + 64], b1y = s_b[d0 + 65];
    #pragma unroll
    for (int i = 0; i < 6; i++) {
        int w = wg * 6 + i;
        float has = s_has[w];
        float a0x, a0y, a1x, a1y;
        unpack2(acc0[i], a0x, a0y);
        unpack2(acc1[i], a1x, a1y);
        s_w[(d0    ) * 49 + w] = a0x + has * b0x;
        s_w[(d0 + 1) * 49 + w] = a0y + has * b0y;
        s_w[(d0 + 64) * 49 + w] = a1x + has * b1x;
        s_w[(d0 + 65) * 49 + w] = a1y + has * b1y;
    }
    __syncthreads();

    // ---- coalesced float4 store of out[b][d][w] ----
    float* obase = out + (size_t)b * DOUT * WIN;
    #pragma unroll
    for (int it = 0; it < 6; it++) {
        int j = it * 1024 + tid * 4;   // 48 % 4 == 0 -> all 4 elems share d
        int d = j / 48;
        int w = j - d * 48;
        const float* src = s_w + d * 49 + w;
        float4 v = make_float4(src[0], src[1], src[2], src[3]);
        *reinterpret_cast<float4*>(obase + j) = v;
    }
}

// ---------------------------------------------------------------------------
extern "C" void kernel_launch(void* const* d_in, const int* in_sizes, int n_in,
                              void* d_out, int out_size) {
    const float* input = (const float*)d_in[0];
    const float* Wm    = (const float*)d_in[1];
    const float* bias  = (const float*)d_in[2];

    const int* bi;
    const int* wi;
    int n_events;
    if (n_in >= 6 && in_sizes[3] == 1) {
        bi = (const int*)d_in[4];
        wi = (const int*)d_in[5];
        n_events = in_sizes[4];
    } else {
        bi = (const int*)d_in[3];
        wi = (const int*)d_in[4];
        n_events = in_sizes[3];
    }

    int eb = (n_events + 255) / 256;

    zero_cnt_kernel<<<(NSEG + 255) / 256, 256>>>();
    hist_kernel<<<eb, 256>>>(bi, wi, n_events);
    scan_a_kernel<<<SCAN_NBLK, 1024>>>();
    scan_c_kernel<<<NSEG / 256, 256>>>();
    scatter_idx_kernel<<<eb, 256>>>(bi, wi, n_events);
    reduce_kernel<<<NSEG / 8, 256>>>(input);
    pool_gemm_kernel<<<BATCH, 256>>>(Wm, bias, (float*)d_out);
}